// round 1
// baseline (speedup 1.0000x reference)
#include <cuda_runtime.h>
#include <math.h>

// ---------------------------------------------------------------------------
// MultiWaveletCross on GB300 — round 1 baseline
// B=16, N=1024, C=64, K=8 (C*K=512=ICH), H=K=8, E=C=64, MODES=16
// Key simplifications: v is dead; FFTs are <=16-mode DFTs; fca(d) reused.
// ---------------------------------------------------------------------------

#define BB 16
#define CKD 512          // C*K
#define NTOK 16384       // B*N
#define PYR 8380416L     // 16*512*(1023)  (sum of per-level Ud/Us sizes)

// Scratch (static __device__ arrays: allocation-free per harness rules)
__device__ float g_QA[8388608];
__device__ float g_QB[8388608];
__device__ float g_KA[8388608];
__device__ float g_KB[8388608];
__device__ float g_DQ[4194304];
__device__ float g_DK[4194304];
__device__ float g_US[8380416];
__device__ float g_UD[8380416];
__device__ float g_VA[8388608];
__device__ float g_VB[8388608];
__device__ float2 g_QF[131072];   // (b,h,e,16) complex
__device__ float2 g_KF[131072];
__device__ float2 g_OF[131072];

// ---------------------------------------------------------------------------
// GEMM: C[M,N] = A[M,Kd] @ W[Kd,N] + bias[N].  128x128 tile, 8x8/thread.
// ---------------------------------------------------------------------------
__global__ __launch_bounds__(256) void gemm_bias(
    const float* __restrict__ A, const float* __restrict__ W,
    const float* __restrict__ bias, float* __restrict__ C,
    int M, int N, int Kd)
{
    __shared__ float As[8][128];
    __shared__ float Ws[8][128];
    const int tid = threadIdx.x;
    const int bm = blockIdx.y * 128, bn = blockIdx.x * 128;
    const int tx = tid & 15, ty = tid >> 4;

    float acc[8][8];
#pragma unroll
    for (int i = 0; i < 8; i++)
#pragma unroll
        for (int j = 0; j < 8; j++) acc[i][j] = 0.f;

    const int arow = tid >> 1, acol = (tid & 1) * 4;
    const int wrow = tid >> 5, wcol = (tid & 31) * 4;
    const float* Aptr = A + (size_t)(bm + arow) * Kd + acol;
    const float* Wptr = W + (size_t)wrow * N + bn + wcol;

    for (int k0 = 0; k0 < Kd; k0 += 8) {
        float4 av = *(const float4*)(Aptr + k0);
        float4 wv = *(const float4*)(Wptr + (size_t)k0 * N);
        As[acol + 0][arow] = av.x; As[acol + 1][arow] = av.y;
        As[acol + 2][arow] = av.z; As[acol + 3][arow] = av.w;
        *(float4*)&Ws[wrow][wcol] = wv;
        __syncthreads();
#pragma unroll
        for (int k = 0; k < 8; k++) {
            float a[8], b[8];
            *(float4*)(a)     = *(const float4*)&As[k][ty * 4];
            *(float4*)(a + 4) = *(const float4*)&As[k][64 + ty * 4];
            *(float4*)(b)     = *(const float4*)&Ws[k][tx * 4];
            *(float4*)(b + 4) = *(const float4*)&Ws[k][64 + tx * 4];
#pragma unroll
            for (int i = 0; i < 8; i++)
#pragma unroll
                for (int j = 0; j < 8; j++)
                    acc[i][j] += a[i] * b[j];
        }
        __syncthreads();
    }
#pragma unroll
    for (int ih = 0; ih < 2; ih++)
#pragma unroll
        for (int i = 0; i < 4; i++) {
            int r = bm + ih * 64 + ty * 4 + i;
#pragma unroll
            for (int jh = 0; jh < 2; jh++) {
                int c = bn + jh * 64 + tx * 4;
                float4 bv = *(const float4*)(bias + c);
                float4 o;
                o.x = acc[ih * 4 + i][jh * 4 + 0] + bv.x;
                o.y = acc[ih * 4 + i][jh * 4 + 1] + bv.y;
                o.z = acc[ih * 4 + i][jh * 4 + 2] + bv.z;
                o.w = acc[ih * 4 + i][jh * 4 + 3] + bv.w;
                *(float4*)(C + (size_t)r * N + c) = o;
            }
        }
}

// ---------------------------------------------------------------------------
// Wavelet step: x (b, 2*Lh, 64, 8) -> d = xa@ec_d, s = xa@ec_s  (b, Lh, 64, 8)
// xa[t2] = [x[2t2, c, :8], x[2t2+1, c, :8]]
// ---------------------------------------------------------------------------
__global__ __launch_bounds__(256) void wavelet_kernel(
    const float* __restrict__ x, const float* __restrict__ ecd,
    const float* __restrict__ ecs, float* __restrict__ od,
    float* __restrict__ os, int Lh)
{
    __shared__ float wd[16][8], ws_[16][8];
    int tid = threadIdx.x;
    if (tid < 128)       wd[tid >> 3][tid & 7] = ecd[tid];
    else if (tid < 256)  { int t = tid - 128; ws_[t >> 3][t & 7] = ecs[t]; }
    __syncthreads();

    long idx = (long)blockIdx.x * 256 + tid;
    long total = (long)BB * Lh * 64;
    if (idx >= total) return;
    int c = (int)(idx & 63);
    long bt = idx >> 6;
    int t2 = (int)(bt % Lh);
    int b = (int)(bt / Lh);

    const float* p0 = x + ((long)(b * 2 * Lh + 2 * t2)) * CKD + c * 8;
    float a[16];
    *(float4*)(a)      = *(const float4*)(p0);
    *(float4*)(a + 4)  = *(const float4*)(p0 + 4);
    *(float4*)(a + 8)  = *(const float4*)(p0 + CKD);
    *(float4*)(a + 12) = *(const float4*)(p0 + CKD + 4);

    float rd[8], rs[8];
#pragma unroll
    for (int kk = 0; kk < 8; kk++) { rd[kk] = 0.f; rs[kk] = 0.f; }
#pragma unroll
    for (int j = 0; j < 16; j++)
#pragma unroll
        for (int kk = 0; kk < 8; kk++) {
            rd[kk] += a[j] * wd[j][kk];
            rs[kk] += a[j] * ws_[j][kk];
        }
    float* pd = od + ((long)(b * Lh + t2)) * CKD + c * 8;
    float* ps = os + ((long)(b * Lh + t2)) * CKD + c * 8;
    *(float4*)(pd)     = *(float4*)(rd);
    *(float4*)(pd + 4) = *(float4*)(rd + 4);
    *(float4*)(ps)     = *(float4*)(rs);
    *(float4*)(ps + 4) = *(float4*)(rs + 4);
}

// ---------------------------------------------------------------------------
// Reconstruction step: s = vin + us; a16 = [s, ud]; e = a16@rc_e; o = a16@rc_o;
// vout[2t] = e, vout[2t+1] = o
// ---------------------------------------------------------------------------
__global__ __launch_bounds__(256) void recon_kernel(
    const float* __restrict__ vin, const float* __restrict__ us,
    const float* __restrict__ ud, const float* __restrict__ rce,
    const float* __restrict__ rco, float* __restrict__ vout, int Lv)
{
    __shared__ float we[16][8], wo[16][8];
    int tid = threadIdx.x;
    if (tid < 128)       we[tid >> 3][tid & 7] = rce[tid];
    else if (tid < 256)  { int t = tid - 128; wo[t >> 3][t & 7] = rco[t]; }
    __syncthreads();

    long idx = (long)blockIdx.x * 256 + tid;
    long total = (long)BB * Lv * 64;
    if (idx >= total) return;
    int c = (int)(idx & 63);
    long bt = idx >> 6;
    int t = (int)(bt % Lv);
    int b = (int)(bt / Lv);

    long base = ((long)(b * Lv + t)) * CKD + c * 8;
    float a[16];
#pragma unroll
    for (int j = 0; j < 8; j++) a[j] = vin[base + j] + us[base + j];
    *(float4*)(a + 8)  = *(const float4*)(ud + base);
    *(float4*)(a + 12) = *(const float4*)(ud + base + 4);

    float re[8], ro[8];
#pragma unroll
    for (int kk = 0; kk < 8; kk++) { re[kk] = 0.f; ro[kk] = 0.f; }
#pragma unroll
    for (int j = 0; j < 16; j++)
#pragma unroll
        for (int kk = 0; kk < 8; kk++) {
            re[kk] += a[j] * we[j][kk];
            ro[kk] += a[j] * wo[j][kk];
        }
    float* pe = vout + ((long)(b * 2 * Lv + 2 * t)) * CKD + c * 8;
    *(float4*)(pe)           = *(float4*)(re);
    *(float4*)(pe + 4)       = *(float4*)(re + 4);
    *(float4*)(pe + CKD)     = *(float4*)(ro);
    *(float4*)(pe + CKD + 4) = *(float4*)(ro + 4);
}

// ---------------------------------------------------------------------------
// rfft (first m modes): F[b,h,e,x] = sum_t x[b,t,e,h] * exp(-2pi i x t / L)
// grid (8 e-chunks, B), 256 threads. Twiddle table of length L (pow2).
// ---------------------------------------------------------------------------
__global__ __launch_bounds__(256) void rfft_kernel(
    const float* __restrict__ x, float2* __restrict__ F, int L, int m)
{
    __shared__ float twc[512], tws[512];
    __shared__ float tile[64][64];
    int tid = threadIdx.x;
    int ec = blockIdx.x;   // e-chunk 0..7
    int b = blockIdx.y;

    for (int i = tid; i < L; i += 256) {
        float th = 6.2831853071795864f * (float)i / (float)L;
        float s, c; sincosf(th, &s, &c);
        twc[i] = c; tws[i] = s;
    }

    int eh = tid >> 2;     // 0..63 : local (e,h)
    int xg = tid & 3;
    float ar[4] = {0.f, 0.f, 0.f, 0.f}, ai[4] = {0.f, 0.f, 0.f, 0.f};

    for (int t0 = 0; t0 < L; t0 += 64) {
        int tc = L - t0 < 64 ? L - t0 : 64;
        __syncthreads();
        for (int i = tid; i < tc * 64; i += 256) {
            int tt = i >> 6, el = i & 63;
            tile[tt][el] = x[((long)(b * L + t0 + tt)) * CKD + ec * 64 + el];
        }
        __syncthreads();
        for (int tt = 0; tt < tc; tt++) {
            float v = tile[tt][eh];
            int t = t0 + tt;
#pragma unroll
            for (int j = 0; j < 4; j++) {
                int xx = xg + j * 4;
                int id = (xx * t) & (L - 1);
                ar[j] += v * twc[id];
                ai[j] -= v * tws[id];
            }
        }
    }
    int e = ec * 8 + (eh >> 3), h = eh & 7;
    float2* dst = F + ((long)((b * 8 + h) * 64 + e)) * 16;
#pragma unroll
    for (int j = 0; j < 4; j++) {
        int xx = xg + j * 4;
        if (xx < m) dst[xx] = make_float2(ar[j], ai[j]);
    }
}

// ---------------------------------------------------------------------------
// attn: S[x,y] = ctanh(sum_e QF[e,x]*KF[e,y]);  OF[e,x] = sum_y S[x,y]*KF[e,y]
// one block per (b,h)
// ---------------------------------------------------------------------------
__global__ __launch_bounds__(256) void attn_kernel(
    const float2* __restrict__ QF, const float2* __restrict__ KF,
    float2* __restrict__ OF, int m)
{
    __shared__ float2 qf[1024], kf[1024], S[256];
    int bh = blockIdx.x, tid = threadIdx.x;
    const float2* qsrc = QF + (long)bh * 1024;
    const float2* ksrc = KF + (long)bh * 1024;
    for (int i = tid; i < 1024; i += 256) { qf[i] = qsrc[i]; kf[i] = ksrc[i]; }
    __syncthreads();

    for (int s = tid; s < m * m; s += 256) {
        int xx = s / m, yy = s - xx * m;
        float re = 0.f, im = 0.f;
#pragma unroll 8
        for (int e = 0; e < 64; e++) {
            float2 qv = qf[e * 16 + xx], kv = kf[e * 16 + yy];
            re += qv.x * kv.x - qv.y * kv.y;
            im += qv.x * kv.y + qv.y * kv.x;
        }
        // complex tanh: (sinh 2a + i sin 2b) / (cosh 2a + cos 2b), saturating
        float X = 2.f * re, Y = 2.f * im, orr, oii;
        if (fabsf(X) > 20.f) {
            orr = copysignf(1.f, X); oii = 0.f;
        } else {
            float ex = expf(X), enx = 1.f / ex;
            float sh = 0.5f * (ex - enx), ch = 0.5f * (ex + enx);
            float sy, cy; sincosf(Y, &sy, &cy);
            float den = ch + cy;
            orr = sh / den; oii = sy / den;
        }
        S[xx * 16 + yy] = make_float2(orr, oii);
    }
    __syncthreads();
    for (int o = tid; o < 64 * m; o += 256) {
        int e = o / m, xx = o - e * m;
        float re = 0.f, im = 0.f;
        for (int yy = 0; yy < m; yy++) {
            float2 sv = S[xx * 16 + yy], kv = kf[e * 16 + yy];
            re += sv.x * kv.x - sv.y * kv.y;
            im += sv.x * kv.y + sv.y * kv.x;
        }
        OF[(long)bh * 1024 + e * 16 + xx] = make_float2(re, im);
    }
}

// ---------------------------------------------------------------------------
// irfft (m low modes, /(L*4096)): out[b,t,e,h] (+ addsrc) written to (b,L,64,8)
// ---------------------------------------------------------------------------
__global__ __launch_bounds__(256) void irfft_kernel(
    const float2* __restrict__ OF, float* __restrict__ out,
    const float* __restrict__ addsrc, int L, int m)
{
    __shared__ float twc[512], tws[512];
    __shared__ float2 of_s[64][16];
    int tid = threadIdx.x, ec = blockIdx.x, b = blockIdx.y;

    for (int i = tid; i < L; i += 256) {
        float th = 6.2831853071795864f * (float)i / (float)L;
        float s, c; sincosf(th, &s, &c);
        twc[i] = c; tws[i] = s;
    }
    float inv = 1.f / ((float)L * 4096.f);
    for (int i = tid; i < 1024; i += 256) {
        int el = i >> 4, xx = i & 15;
        int e = ec * 8 + (el >> 3), h = el & 7;
        float2 v = (xx < m) ? OF[((long)((b * 8 + h) * 64 + e)) * 16 + xx]
                            : make_float2(0.f, 0.f);
        float w = (xx == 0) ? inv : 2.f * inv;
        of_s[el][xx] = make_float2(v.x * w, v.y * w);
    }
    __syncthreads();

    for (long i = tid; i < (long)L * 64; i += 256) {
        int el = (int)(i & 63);
        int t = (int)(i >> 6);
        float acc = 0.f;
#pragma unroll
        for (int xx = 0; xx < 16; xx++) {
            int id = (xx * t) & (L - 1);
            float2 f = of_s[el][xx];
            acc += f.x * twc[id] - f.y * tws[id];
        }
        long dst = ((long)(b * L + t)) * CKD + ec * 64 + el;
        out[dst] = acc + (addsrc ? addsrc[dst] : 0.f);
    }
}

__global__ void zero_kernel(float* p, long n) {
    long i = (long)blockIdx.x * blockDim.x + threadIdx.x;
    if (i < n) p[i] = 0.f;
}

// ---------------------------------------------------------------------------
extern "C" void kernel_launch(void* const* d_in, const int* in_sizes, int n_in,
                              void* d_out, int out_size)
{
    const float* q    = (const float*)d_in[0];
    const float* k    = (const float*)d_in[1];
    const float* Lq_w = (const float*)d_in[3];
    const float* Lq_b = (const float*)d_in[4];
    const float* Lk_w = (const float*)d_in[5];
    const float* Lk_b = (const float*)d_in[6];
    const float* out_w = (const float*)d_in[9];
    const float* out_b = (const float*)d_in[10];
    const float* ec_s = (const float*)d_in[11];
    const float* ec_d = (const float*)d_in[12];
    const float* rc_e = (const float*)d_in[13];
    const float* rc_o = (const float*)d_in[14];

    float *QA, *QB, *KA, *KB, *DQ, *DK, *US, *UD, *VA, *VB;
    float2 *QF, *KF, *OF;
    cudaGetSymbolAddress((void**)&QA, g_QA);
    cudaGetSymbolAddress((void**)&QB, g_QB);
    cudaGetSymbolAddress((void**)&KA, g_KA);
    cudaGetSymbolAddress((void**)&KB, g_KB);
    cudaGetSymbolAddress((void**)&DQ, g_DQ);
    cudaGetSymbolAddress((void**)&DK, g_DK);
    cudaGetSymbolAddress((void**)&US, g_US);
    cudaGetSymbolAddress((void**)&UD, g_UD);
    cudaGetSymbolAddress((void**)&VA, g_VA);
    cudaGetSymbolAddress((void**)&VB, g_VB);
    cudaGetSymbolAddress((void**)&QF, g_QF);
    cudaGetSymbolAddress((void**)&KF, g_KF);
    cudaGetSymbolAddress((void**)&OF, g_OF);

    dim3 gg(4, 128);   // N=512/128, M=16384/128
    gemm_bias<<<gg, 256>>>(q, Lq_w, Lq_b, QA, NTOK, CKD, CKD);
    gemm_bias<<<gg, 256>>>(k, Lk_w, Lk_b, KA, NTOK, CKD, CKD);

    float* qc = QA; float* qn = QB;
    float* kc = KA; float* kn = KB;
    long offs[10]; int Lhs[10];
    long off = 0;
    int L = 1024;
    for (int i = 0; i < 10; i++) {
        int Lh = L >> 1;
        Lhs[i] = Lh; offs[i] = off;
        off += (long)BB * Lh * CKD;
        int m = (Lh / 2 < 16) ? (Lh / 2) : 16;
        long total = (long)BB * Lh * 64;
        int blocks = (int)((total + 255) / 256);

        wavelet_kernel<<<blocks, 256>>>(qc, ec_d, ec_s, DQ, qn, Lh);
        wavelet_kernel<<<blocks, 256>>>(kc, ec_d, ec_s, DK, kn, Lh);

        long sz = (long)BB * Lh * CKD;
        if (m > 0) {
            dim3 fg(8, BB);
            // Us[i] = fca(dq, dk)
            rfft_kernel<<<fg, 256>>>(DQ, QF, Lh, m);
            rfft_kernel<<<fg, 256>>>(DK, KF, Lh, m);
            attn_kernel<<<128, 256>>>(QF, KF, OF, m);
            irfft_kernel<<<fg, 256>>>(OF, US + offs[i], nullptr, Lh, m);
            // Ud[i] = fca(q, k) + Us[i]
            rfft_kernel<<<fg, 256>>>(qn, QF, Lh, m);
            rfft_kernel<<<fg, 256>>>(kn, KF, Lh, m);
            attn_kernel<<<128, 256>>>(QF, KF, OF, m);
            irfft_kernel<<<fg, 256>>>(OF, UD + offs[i], US + offs[i], Lh, m);
        } else {
            zero_kernel<<<(int)((sz + 255) / 256), 256>>>(US + offs[i], sz);
            zero_kernel<<<(int)((sz + 255) / 256), 256>>>(UD + offs[i], sz);
        }
        { float* t = qc; qc = qn; qn = t; }
        { float* t = kc; kc = kn; kn = t; }
        L = Lh;
    }

    // Final fca on L=1 is exactly zero -> v starts as zeros, length 1
    zero_kernel<<<32, 256>>>(VA, (long)BB * 1 * CKD);
    float* vc = VA; float* vn = VB;
    for (int i = 9; i >= 0; i--) {
        int Lv = Lhs[i];
        long total = (long)BB * Lv * 64;
        recon_kernel<<<(int)((total + 255) / 256), 256>>>(
            vc, US + offs[i], UD + offs[i], rc_e, rc_o, vn, Lv);
        float* t = vc; vc = vn; vn = t;
    }

    // Output projection
    gemm_bias<<<gg, 256>>>(vc, out_w, out_b, (float*)d_out, NTOK, CKD, CKD);
}